// round 1
// baseline (speedup 1.0000x reference)
#include <cuda_runtime.h>
#include <math.h>

// Problem constants (fixed by the reference setup_inputs)
#define MPTS   4096
#define KPTS   4096
#define NBATCH 4
#define NITERS 50
#define NT     256
#define GRIDR  512          // row-pass blocks; 512 * 8 rows = 4096
#define ROWSPB 8
#define INV_N  (1.0f/4096.0f)
#define SURV_THRESH 1e-5f

// Scratch (device globals; allocation-free per harness rules).
// One batch's Gibbs kernel at a time (batches run sequentially) -> stays L2-resident.
__device__ float g_K[(size_t)MPTS * KPTS];      // 64 MB
__device__ float g_u[MPTS];
__device__ float g_v[KPTS];
__device__ float g_Tpart[GRIDR][KPTS];          // 8 MB per-block column partials
__device__ float g_cmaxpart[GRIDR];
__device__ float g_losspart[NBATCH][GRIDR][3];  // cnt, velsq, bce

__device__ __forceinline__ float warpMax(float v){
    #pragma unroll
    for (int o = 16; o; o >>= 1) v = fmaxf(v, __shfl_xor_sync(0xffffffffu, v, o));
    return v;
}
__device__ __forceinline__ float warpSum(float v){
    #pragma unroll
    for (int o = 16; o; o >>= 1) v += __shfl_xor_sync(0xffffffffu, v, o);
    return v;
}

// ---------------------------------------------------------------------------
// Pass 1: per-block max of the cost matrix (recomputed on the fly; C = |x0-xg|^2)
// ---------------------------------------------------------------------------
__global__ void __launch_bounds__(NT) k_cmax(const float* __restrict__ x0,
                                             const float* __restrict__ xg){
    int t = threadIdx.x, blk = blockIdx.x;
    int r0 = blk * ROWSPB;
    float mx = 0.f;
    for (int r = 0; r < ROWSPB; r++){
        int i = r0 + r;
        float ax = x0[3*i], ay = x0[3*i+1], az = x0[3*i+2];
        #pragma unroll
        for (int k = 0; k < 4; k++){
            int j0 = 4*t + 1024*k;
            #pragma unroll
            for (int c = 0; c < 4; c++){
                int j = j0 + c;
                float dx = ax - xg[3*j], dy = ay - xg[3*j+1], dz = az - xg[3*j+2];
                mx = fmaxf(mx, dx*dx + dy*dy + dz*dz);
            }
        }
    }
    __shared__ float sm[8];
    mx = warpMax(mx);
    if ((t & 31) == 0) sm[t >> 5] = mx;
    __syncthreads();
    if (t == 0){
        float m = sm[0];
        #pragma unroll
        for (int w = 1; w < 8; w++) m = fmaxf(m, sm[w]);
        g_cmaxpart[blk] = m;
    }
}

// ---------------------------------------------------------------------------
// Pass 2: K_ij = exp(-C_ij / (cmax*reg)), computed once; also init v = 1.
// ---------------------------------------------------------------------------
__global__ void __launch_bounds__(NT) k_expK(const float* __restrict__ x0,
                                             const float* __restrict__ xg){
    int t = threadIdx.x, blk = blockIdx.x;
    __shared__ float sm[8];
    __shared__ float s_scale;
    float m = 0.f;
    for (int p = t; p < GRIDR; p += NT) m = fmaxf(m, g_cmaxpart[p]);
    m = warpMax(m);
    if ((t & 31) == 0) sm[t >> 5] = m;
    __syncthreads();
    if (t == 0){
        float mm = sm[0];
        #pragma unroll
        for (int w = 1; w < 8; w++) mm = fmaxf(mm, sm[w]);
        // exponent = -C/(cmax*reg); convert to base-2: * log2(e)
        s_scale = -1.44269504088896340736f / (0.1f * mm);
    }
    __syncthreads();
    float scale = s_scale;
    int r0 = blk * ROWSPB;
    for (int r = 0; r < ROWSPB; r++){
        int i = r0 + r;
        float ax = x0[3*i], ay = x0[3*i+1], az = x0[3*i+2];
        #pragma unroll
        for (int k = 0; k < 4; k++){
            int j0 = 4*t + 1024*k;
            float4 out;
            float* o = (float*)&out;
            #pragma unroll
            for (int c = 0; c < 4; c++){
                int j = j0 + c;
                float dx = ax - xg[3*j], dy = ay - xg[3*j+1], dz = az - xg[3*j+2];
                float C = dx*dx + dy*dy + dz*dz;
                o[c] = exp2f(C * scale);
            }
            *(float4*)&g_K[(size_t)i * KPTS + j0] = out;
        }
    }
    if (blk == 0){
        for (int j = t; j < KPTS; j += NT) g_v[j] = 1.0f;   // g = 0
    }
}

// ---------------------------------------------------------------------------
// Fused Sinkhorn half-iteration: one pass over K computes
//   u_i = a / (K v)_i  AND  per-block column partials  Tpart_j += K_ij * u_i
// (u_i only depends on row i, which this block owns -> no inter-block sync).
// K row is held in registers between the two uses -> K read ONCE per iteration.
// ---------------------------------------------------------------------------
__global__ void __launch_bounds__(NT) k_rowpass(){
    int t = threadIdx.x, blk = blockIdx.x, warp = t >> 5, lane = t & 31;
    __shared__ float sred[2][8];
    int r0 = blk * ROWSPB;

    float4 vreg[4];
    #pragma unroll
    for (int k = 0; k < 4; k++) vreg[k] = *(const float4*)&g_v[4*t + 1024*k];

    float4 Tacc[4];
    #pragma unroll
    for (int k = 0; k < 4; k++) Tacc[k] = make_float4(0.f, 0.f, 0.f, 0.f);

    const float4* Kf = (const float4*)g_K;
    float4 kv[4];
    #pragma unroll
    for (int k = 0; k < 4; k++) kv[k] = Kf[(size_t)r0 * 1024 + t + 256*k];

    for (int r = 0; r < ROWSPB; r++){
        int i = r0 + r;
        float4 kn[4];
        if (r + 1 < ROWSPB){
            #pragma unroll
            for (int k = 0; k < 4; k++) kn[k] = Kf[(size_t)(i+1) * 1024 + t + 256*k];
        } else {
            #pragma unroll
            for (int k = 0; k < 4; k++) kn[k] = make_float4(0.f, 0.f, 0.f, 0.f);
        }
        float s = 0.f;
        #pragma unroll
        for (int k = 0; k < 4; k++){
            s = fmaf(kv[k].x, vreg[k].x, s); s = fmaf(kv[k].y, vreg[k].y, s);
            s = fmaf(kv[k].z, vreg[k].z, s); s = fmaf(kv[k].w, vreg[k].w, s);
        }
        s = warpSum(s);
        if (lane == 0) sred[r & 1][warp] = s;
        __syncthreads();
        float S = 0.f;
        #pragma unroll
        for (int w = 0; w < 8; w++) S += sred[r & 1][w];
        float u = INV_N / S;
        if (t == 0) g_u[i] = u;
        #pragma unroll
        for (int k = 0; k < 4; k++){
            Tacc[k].x = fmaf(kv[k].x, u, Tacc[k].x);
            Tacc[k].y = fmaf(kv[k].y, u, Tacc[k].y);
            Tacc[k].z = fmaf(kv[k].z, u, Tacc[k].z);
            Tacc[k].w = fmaf(kv[k].w, u, Tacc[k].w);
        }
        #pragma unroll
        for (int k = 0; k < 4; k++) kv[k] = kn[k];
        // parity-buffered sred: next row writes the other slot; a barrier always
        // separates a slot's reads from its next writes.
    }
    #pragma unroll
    for (int k = 0; k < 4; k++)
        *(float4*)&g_Tpart[blk][4*t + 1024*k] = Tacc[k];
}

// ---------------------------------------------------------------------------
// v_j = b / sum_p Tpart[p][j]  (deterministic tree: fixed p order per group)
// grid: KPTS/32 = 128 blocks x 256 threads; 8 p-groups of 64 per column.
// ---------------------------------------------------------------------------
__global__ void __launch_bounds__(NT) k_colfix(){
    int t = threadIdx.x, blk = blockIdx.x;
    int c = t & 31, pg = t >> 5;            // 32 columns, 8 partial-groups
    int j = blk * 32 + c;
    float s = 0.f;
    int p0 = pg * (GRIDR / 8);
    #pragma unroll 8
    for (int p = p0; p < p0 + (GRIDR / 8); p++) s += g_Tpart[p][j];
    __shared__ float sm[8][32];
    sm[pg][c] = s;
    __syncthreads();
    if (t < 32){
        float T = 0.f;
        #pragma unroll
        for (int g = 0; g < 8; g++) T += sm[g][t];
        g_v[blk * 32 + t] = INV_N / T;
    }
}

// ---------------------------------------------------------------------------
// Final per-batch pass: row argmax of pi_ij = u_i * K_ij * v_j, survival,
// velocity-loss and BCE partial sums per block.
// ---------------------------------------------------------------------------
__global__ void __launch_bounds__(NT) k_final(const float* __restrict__ x0,
                                              const float* __restrict__ xg,
                                              const float* __restrict__ vp,
                                              const float* __restrict__ alpha,
                                              int b){
    int t = threadIdx.x, blk = blockIdx.x, warp = t >> 5, lane = t & 31;
    __shared__ float smx[8];
    __shared__ int   smi[8];
    int r0 = blk * ROWSPB;

    float4 vreg[4];
    #pragma unroll
    for (int k = 0; k < 4; k++) vreg[k] = *(const float4*)&g_v[4*t + 1024*k];

    float cnt = 0.f, velsq = 0.f, bce = 0.f;   // accumulated by thread 0 only

    for (int r = 0; r < ROWSPB; r++){
        int i = r0 + r;
        float m = -1.f; int mi = 0;
        #pragma unroll
        for (int k = 0; k < 4; k++){
            float4 kv = *(const float4*)&g_K[(size_t)i * KPTS + 4*t + 1024*k];
            int j0 = 4*t + 1024*k;
            float p0 = kv.x * vreg[k].x, p1 = kv.y * vreg[k].y;
            float p2 = kv.z * vreg[k].z, p3 = kv.w * vreg[k].w;
            if (p0 > m){ m = p0; mi = j0;     }
            if (p1 > m){ m = p1; mi = j0 + 1; }
            if (p2 > m){ m = p2; mi = j0 + 2; }
            if (p3 > m){ m = p3; mi = j0 + 3; }
        }
        // warp argmax (ties -> smallest index, matching jnp.argmax)
        #pragma unroll
        for (int o = 16; o; o >>= 1){
            float om = __shfl_xor_sync(0xffffffffu, m, o);
            int   oi = __shfl_xor_sync(0xffffffffu, mi, o);
            if (om > m || (om == m && oi < mi)){ m = om; mi = oi; }
        }
        if (lane == 0){ smx[warp] = m; smi[warp] = mi; }
        __syncthreads();
        if (t == 0){
            #pragma unroll
            for (int w = 1; w < 8; w++){
                if (smx[w] > m || (smx[w] == m && smi[w] < mi)){ m = smx[w]; mi = smi[w]; }
            }
            float p = g_u[i] * m;               // max transport prob of row i
            float a_i = alpha[i];
            // stable softplus, matches jax.nn.softplus
            float sp = fmaxf(a_i, 0.f) + log1pf(expf(-fabsf(a_i)));
            bce += sp;
            if (p > SURV_THRESH){
                cnt += 1.f;
                bce -= a_i;
                #pragma unroll
                for (int d = 0; d < 3; d++){
                    float vt = xg[3*mi + d] - x0[3*i + d];
                    float df = vp[3*i + d] - vt;
                    velsq = fmaf(df, df, velsq);
                }
            }
        }
        __syncthreads();
    }
    if (t == 0){
        g_losspart[b][blk][0] = cnt;
        g_losspart[b][blk][1] = velsq;
        g_losspart[b][blk][2] = bce;
    }
}

// ---------------------------------------------------------------------------
// Final scalar reduction across all batches/blocks.
// ---------------------------------------------------------------------------
__global__ void __launch_bounds__(NT) k_loss(float* __restrict__ out){
    int t = threadIdx.x;
    float cnt = 0.f, velsq = 0.f, bce = 0.f;
    for (int idx = t; idx < NBATCH * GRIDR; idx += NT){
        int b = idx / GRIDR, p = idx % GRIDR;
        cnt   += g_losspart[b][p][0];
        velsq += g_losspart[b][p][1];
        bce   += g_losspart[b][p][2];
    }
    cnt = warpSum(cnt); velsq = warpSum(velsq); bce = warpSum(bce);
    __shared__ float sc[8], sv[8], sb[8];
    if ((t & 31) == 0){ sc[t>>5] = cnt; sv[t>>5] = velsq; sb[t>>5] = bce; }
    __syncthreads();
    if (t == 0){
        float C = 0.f, V = 0.f, Bc = 0.f;
        #pragma unroll
        for (int w = 0; w < 8; w++){ C += sc[w]; V += sv[w]; Bc += sb[w]; }
        float denom = fmaxf(C, 1.f);
        out[0] = V / denom + Bc / (float)(NBATCH * MPTS);
    }
}

// ---------------------------------------------------------------------------
extern "C" void kernel_launch(void* const* d_in, const int* in_sizes, int n_in,
                              void* d_out, int out_size){
    const float* x0 = (const float*)d_in[0];   // (B, M, 3)
    const float* xg = (const float*)d_in[1];   // (B, K, 3)
    const float* vp = (const float*)d_in[2];   // (B, M, 3)
    const float* al = (const float*)d_in[3];   // (B, M, 1)
    (void)in_sizes; (void)n_in; (void)out_size;

    for (int b = 0; b < NBATCH; b++){
        const float* x0b = x0 + (size_t)b * MPTS * 3;
        const float* xgb = xg + (size_t)b * KPTS * 3;
        k_cmax<<<GRIDR, NT>>>(x0b, xgb);
        k_expK<<<GRIDR, NT>>>(x0b, xgb);
        for (int it = 0; it < NITERS; it++){
            k_rowpass<<<GRIDR, NT>>>();
            k_colfix<<<KPTS / 32, NT>>>();
        }
        k_final<<<GRIDR, NT>>>(x0b, xgb,
                               vp + (size_t)b * MPTS * 3,
                               al + (size_t)b * MPTS, b);
    }
    k_loss<<<1, NT>>>((float*)d_out);
}

// round 2
// speedup vs baseline: 1.4198x; 1.4198x over previous
#include <cuda_runtime.h>
#include <cuda_fp16.h>
#include <math.h>

// Problem constants (fixed by the reference setup_inputs)
#define MPTS   4096
#define KPTS   4096
#define NBATCH 4
#define NITERS 50
#define GRID   256          // persistent blocks (co-resident: 148 SMs x 2)
#define NT     256
#define ROWSPB 16           // 4096 / 256
#define INV_N  (1.0f/4096.0f)
#define SURV_THRESH 1e-5f
#define NBARS  (2 + 2*NITERS)   // grid barriers per batch

// Scratch (device globals; allocation-free per harness rules).
__device__ __half g_K16[(size_t)MPTS * KPTS];     // 32 MB, L2-resident per batch
__device__ float  g_u[MPTS];
__device__ float  g_v[KPTS];
__device__ float  g_Tpart[GRID][KPTS];            // 4 MB column partials
__device__ float  g_cmaxpart[GRID];
__device__ float  g_losspart[NBATCH][GRID][3];    // cnt, velsq, bce
__device__ unsigned g_barcnt;                     // grid-barrier counter

__device__ __forceinline__ float warpMax(float v){
    #pragma unroll
    for (int o = 16; o; o >>= 1) v = fmaxf(v, __shfl_xor_sync(0xffffffffu, v, o));
    return v;
}
__device__ __forceinline__ float warpSum(float v){
    #pragma unroll
    for (int o = 16; o; o >>= 1) v += __shfl_xor_sync(0xffffffffu, v, o);
    return v;
}
__device__ __forceinline__ float ex2(float x){
    float r; asm("ex2.approx.f32 %0, %1;" : "=f"(r) : "f"(x)); return r;
}

// Software grid barrier. All GRID blocks are co-resident (launch_bounds(256,2)
// guarantees >=2 blocks/SM -> capacity 296 >= 256). tgt advances by GRID.
__device__ __forceinline__ void gbar(unsigned &tgt){
    __syncthreads();
    if (threadIdx.x == 0){
        __threadfence();
        atomicAdd(&g_barcnt, 1u);
        while (*((volatile unsigned*)&g_barcnt) < tgt) __nanosleep(64);
    }
    __syncthreads();
    tgt += GRID;
}

// Convert two uint4s (16 halfs) of a K row to float.
__device__ __forceinline__ void cvt16(const uint4 &a, const uint4 &b, float *kf){
    const __half2* ha = (const __half2*)&a;
    const __half2* hb = (const __half2*)&b;
    #pragma unroll
    for (int q = 0; q < 4; q++){
        float2 f = __half22float2(ha[q]); kf[2*q]   = f.x; kf[2*q+1]   = f.y;
        float2 g = __half22float2(hb[q]); kf[8+2*q] = g.x; kf[8+2*q+1] = g.y;
    }
}

// ---------------------------------------------------------------------------
// One persistent kernel per batch: cmax -> exp(K16) -> 50 Sinkhorn iterations
// (fused row pass + column fix, separated by grid barriers) -> argmax/loss.
// ---------------------------------------------------------------------------
__global__ void __launch_bounds__(NT, 2) k_persist(
        const float* __restrict__ x0, const float* __restrict__ xg,
        const float* __restrict__ vp, const float* __restrict__ alpha,
        int b, unsigned base)
{
    int t = threadIdx.x, blk = blockIdx.x, warp = t >> 5, lane = t & 31;
    __shared__ float sred[2][8];
    __shared__ float sB[16][17];
    __shared__ float s_scalar;
    __shared__ float smx[8];
    __shared__ int   smi[8];
    unsigned tgt = base + GRID;
    int r0 = blk * ROWSPB;

    // Thread t owns columns j = 8t..8t+7 and 2048+8t..2048+8t+7.
    // Load those 16 goal points (setup/final phases only).
    float gx[16], gy[16], gz[16];
    #pragma unroll
    for (int h = 0; h < 2; h++){
        const float* base_g = xg + (size_t)h * 2048 * 3 + 24 * t;
        #pragma unroll
        for (int c = 0; c < 8; c++){
            gx[8*h+c] = base_g[3*c];
            gy[8*h+c] = base_g[3*c+1];
            gz[8*h+c] = base_g[3*c+2];
        }
    }

    // ---- Phase 0: block-local cost max -----------------------------------
    {
        float mx = 0.f;
        for (int r = 0; r < ROWSPB; r++){
            int i = r0 + r;
            float ax = x0[3*i], ay = x0[3*i+1], az = x0[3*i+2];
            #pragma unroll
            for (int c = 0; c < 16; c++){
                float dx = ax-gx[c], dy = ay-gy[c], dz = az-gz[c];
                mx = fmaxf(mx, dx*dx + dy*dy + dz*dz);
            }
        }
        mx = warpMax(mx);
        if (lane == 0) sred[0][warp] = mx;
        __syncthreads();
        if (t == 0){
            float m = sred[0][0];
            #pragma unroll
            for (int w = 1; w < 8; w++) m = fmaxf(m, sred[0][w]);
            g_cmaxpart[blk] = m;
        }
    }
    gbar(tgt);

    // ---- Phase 1: global max -> scale; K16 = 2^4 * exp(-C/(reg*cmax)) ----
    {
        float mc = __ldcg(&g_cmaxpart[t]);     // exactly GRID==NT values
        mc = warpMax(mc);
        if (lane == 0) sred[0][warp] = mc;
        __syncthreads();
        if (t == 0){
            float m = sred[0][0];
            #pragma unroll
            for (int w = 1; w < 8; w++) m = fmaxf(m, sred[0][w]);
            s_scalar = -1.44269504088896340736f / (0.1f * m);
        }
        __syncthreads();
        float scale = s_scalar;
        for (int r = 0; r < ROWSPB; r++){
            int i = r0 + r;
            float ax = x0[3*i], ay = x0[3*i+1], az = x0[3*i+2];
            __half2 hk[8];
            #pragma unroll
            for (int c = 0; c < 16; c += 2){
                float dx = ax-gx[c],   dy = ay-gy[c],   dz = az-gz[c];
                float C0 = dx*dx + dy*dy + dz*dz;
                float e0 = ex2(fmaf(C0, scale, 4.0f));      // +4: 2^4 scaling
                dx = ax-gx[c+1]; dy = ay-gy[c+1]; dz = az-gz[c+1];
                float C1 = dx*dx + dy*dy + dz*dz;
                float e1 = ex2(fmaf(C1, scale, 4.0f));
                hk[c/2] = __floats2half2_rn(e0, e1);
            }
            uint4* Krow = (uint4*)(g_K16 + (size_t)i * KPTS);
            Krow[t]       = *(uint4*)&hk[0];
            Krow[256 + t] = *(uint4*)&hk[4];
        }
        if (blk == 0){
            #pragma unroll
            for (int q = 0; q < 16; q++) g_v[t + 256*q] = 1.0f;
        }
    }
    gbar(tgt);

    // ---- Phase 2: 50 Sinkhorn iterations ---------------------------------
    for (int it = 0; it < NITERS; it++){
        // load v (cross-block data -> L2)
        float vr[16];
        {
            float4 v0 = __ldcg((const float4*)(g_v + 8*t));
            float4 v1 = __ldcg((const float4*)(g_v + 8*t + 4));
            float4 v2 = __ldcg((const float4*)(g_v + 2048 + 8*t));
            float4 v3 = __ldcg((const float4*)(g_v + 2048 + 8*t + 4));
            vr[0]=v0.x; vr[1]=v0.y; vr[2]=v0.z;  vr[3]=v0.w;
            vr[4]=v1.x; vr[5]=v1.y; vr[6]=v1.z;  vr[7]=v1.w;
            vr[8]=v2.x; vr[9]=v2.y; vr[10]=v2.z; vr[11]=v2.w;
            vr[12]=v3.x; vr[13]=v3.y; vr[14]=v3.z; vr[15]=v3.w;
        }
        float Tacc[16];
        #pragma unroll
        for (int c = 0; c < 16; c++) Tacc[c] = 0.f;

        const uint4* K0 = (const uint4*)(g_K16 + (size_t)r0 * KPTS);
        uint4 ka = K0[t], kb = K0[256 + t];

        for (int r = 0; r < ROWSPB; r++){
            int i = r0 + r;
            float kf[16];
            cvt16(ka, kb, kf);
            if (r + 1 < ROWSPB){                 // prefetch next row
                const uint4* Kn = (const uint4*)(g_K16 + (size_t)(i+1) * KPTS);
                ka = Kn[t]; kb = Kn[256 + t];
            }
            float s = 0.f;
            #pragma unroll
            for (int c = 0; c < 16; c++) s = fmaf(kf[c], vr[c], s);
            s = warpSum(s);
            if (lane == 0) sred[r & 1][warp] = s;
            __syncthreads();
            float S = 0.f;
            #pragma unroll
            for (int w = 0; w < 8; w++) S += sred[r & 1][w];
            float u = INV_N / S;
            if (t == 0) g_u[i] = u;
            #pragma unroll
            for (int c = 0; c < 16; c++) Tacc[c] = fmaf(kf[c], u, Tacc[c]);
        }
        // store column partials
        float4* Tp = (float4*)&g_Tpart[blk][0];
        Tp[2*t]       = make_float4(Tacc[0],  Tacc[1],  Tacc[2],  Tacc[3]);
        Tp[2*t+1]     = make_float4(Tacc[4],  Tacc[5],  Tacc[6],  Tacc[7]);
        Tp[512+2*t]   = make_float4(Tacc[8],  Tacc[9],  Tacc[10], Tacc[11]);
        Tp[512+2*t+1] = make_float4(Tacc[12], Tacc[13], Tacc[14], Tacc[15]);
        gbar(tgt);

        // column fix: block handles 16 columns, 16 partial-groups of 16
        {
            int c = t & 15, pg = t >> 4;
            int j = blk * 16 + c;
            float s = 0.f;
            #pragma unroll
            for (int q = 0; q < 16; q++) s += __ldcg(&g_Tpart[pg*16 + q][j]);
            sB[pg][c] = s;
            __syncthreads();
            if (t < 16){
                float T = 0.f;
                #pragma unroll
                for (int g = 0; g < 16; g++) T += sB[g][t];
                g_v[blk*16 + t] = INV_N / T;
            }
        }
        gbar(tgt);
    }

    // ---- Phase 3: argmax of pi = u*K16*v, survival, loss partials --------
    {
        float vr[16];
        {
            float4 v0 = __ldcg((const float4*)(g_v + 8*t));
            float4 v1 = __ldcg((const float4*)(g_v + 8*t + 4));
            float4 v2 = __ldcg((const float4*)(g_v + 2048 + 8*t));
            float4 v3 = __ldcg((const float4*)(g_v + 2048 + 8*t + 4));
            vr[0]=v0.x; vr[1]=v0.y; vr[2]=v0.z;  vr[3]=v0.w;
            vr[4]=v1.x; vr[5]=v1.y; vr[6]=v1.z;  vr[7]=v1.w;
            vr[8]=v2.x; vr[9]=v2.y; vr[10]=v2.z; vr[11]=v2.w;
            vr[12]=v3.x; vr[13]=v3.y; vr[14]=v3.z; vr[15]=v3.w;
        }
        float cnt = 0.f, velsq = 0.f, bce = 0.f;   // thread 0 accumulates
        for (int r = 0; r < ROWSPB; r++){
            int i = r0 + r;
            const uint4* Kr = (const uint4*)(g_K16 + (size_t)i * KPTS);
            uint4 ka = Kr[t], kb = Kr[256 + t];
            float kf[16];
            cvt16(ka, kb, kf);
            float m = -1.f; int mi = 0;
            #pragma unroll
            for (int c = 0; c < 16; c++){
                float p = kf[c] * vr[c];
                int j = (c < 8) ? (8*t + c) : (2048 + 8*t + c - 8);
                if (p > m){ m = p; mi = j; }
            }
            // warp argmax, ties -> smallest index (matches jnp.argmax)
            #pragma unroll
            for (int o = 16; o; o >>= 1){
                float om = __shfl_xor_sync(0xffffffffu, m, o);
                int   oi = __shfl_xor_sync(0xffffffffu, mi, o);
                if (om > m || (om == m && oi < mi)){ m = om; mi = oi; }
            }
            if (lane == 0){ smx[warp] = m; smi[warp] = mi; }
            __syncthreads();
            if (t == 0){
                #pragma unroll
                for (int w = 1; w < 8; w++){
                    if (smx[w] > m || (smx[w] == m && smi[w] < mi)){
                        m = smx[w]; mi = smi[w];
                    }
                }
                float p = g_u[i] * m;               // row-max transport prob
                float a_i = alpha[i];
                float sp = fmaxf(a_i, 0.f) + log1pf(expf(-fabsf(a_i)));
                bce += sp;
                if (p > SURV_THRESH){
                    cnt += 1.f;
                    bce -= a_i;
                    #pragma unroll
                    for (int d = 0; d < 3; d++){
                        float vt = xg[3*mi + d] - x0[3*i + d];
                        float df = vp[3*i + d] - vt;
                        velsq = fmaf(df, df, velsq);
                    }
                }
            }
            __syncthreads();
        }
        if (t == 0){
            g_losspart[b][blk][0] = cnt;
            g_losspart[b][blk][1] = velsq;
            g_losspart[b][blk][2] = bce;
        }
    }
}

// ---------------------------------------------------------------------------
__global__ void k_reset(){ g_barcnt = 0u; }

__global__ void __launch_bounds__(NT) k_loss(float* __restrict__ out){
    int t = threadIdx.x;
    float cnt = 0.f, velsq = 0.f, bce = 0.f;
    for (int idx = t; idx < NBATCH * GRID; idx += NT){
        int b = idx / GRID, p = idx % GRID;
        cnt   += g_losspart[b][p][0];
        velsq += g_losspart[b][p][1];
        bce   += g_losspart[b][p][2];
    }
    cnt = warpSum(cnt); velsq = warpSum(velsq); bce = warpSum(bce);
    __shared__ float sc[8], sv[8], sb[8];
    if ((t & 31) == 0){ sc[t>>5] = cnt; sv[t>>5] = velsq; sb[t>>5] = bce; }
    __syncthreads();
    if (t == 0){
        float C = 0.f, V = 0.f, Bc = 0.f;
        #pragma unroll
        for (int w = 0; w < 8; w++){ C += sc[w]; V += sv[w]; Bc += sb[w]; }
        float denom = fmaxf(C, 1.f);
        out[0] = V / denom + Bc / (float)(NBATCH * MPTS);
    }
}

// ---------------------------------------------------------------------------
extern "C" void kernel_launch(void* const* d_in, const int* in_sizes, int n_in,
                              void* d_out, int out_size){
    const float* x0 = (const float*)d_in[0];   // (B, M, 3)
    const float* xg = (const float*)d_in[1];   // (B, K, 3)
    const float* vp = (const float*)d_in[2];   // (B, M, 3)
    const float* al = (const float*)d_in[3];   // (B, M, 1)
    (void)in_sizes; (void)n_in; (void)out_size;

    k_reset<<<1, 1>>>();
    for (int b = 0; b < NBATCH; b++){
        k_persist<<<GRID, NT>>>(x0 + (size_t)b * MPTS * 3,
                                xg + (size_t)b * KPTS * 3,
                                vp + (size_t)b * MPTS * 3,
                                al + (size_t)b * MPTS,
                                b, (unsigned)(b * NBARS * GRID));
    }
    k_loss<<<1, NT>>>((float*)d_out);
}

// round 3
// speedup vs baseline: 2.1191x; 1.4925x over previous
#include <cuda_runtime.h>
#include <cuda_fp16.h>
#include <math.h>

// Problem constants (fixed by the reference setup_inputs)
#define MPTS   4096
#define NBATCH 4
#define NITERS 50
#define NSLOTS 2            // batches processed concurrently per launch
#define GB     128          // blocks per batch slot
#define NT     256
#define ROWSPB 32           // 4096 / 128
#define CR     8            // rows per chunk (two-pass unit)
#define NCH    (ROWSPB/CR)  // 4 chunks
#define INV_N  (1.0f/4096.0f)
#define SURV_THRESH 1e-5f
#define NBARS  (2 + 2*NITERS)   // grid barriers per slot per launch

// Scratch (device globals; allocation-free per harness rules).
__device__ __half g_K16[NSLOTS][(size_t)MPTS * MPTS];   // 2 x 32 MB, L2-resident
__device__ float  g_u[NSLOTS][MPTS];
__device__ float  g_v[NSLOTS][MPTS];
__device__ float  g_T[NSLOTS][GB][MPTS];                // 2 x 2 MB column partials
__device__ float  g_cmax[NSLOTS][GB];
__device__ float  g_loss[NBATCH][GB][3];                // cnt, velsq, bce
__device__ unsigned g_bar[NSLOTS];                      // per-slot barrier counters

__device__ __forceinline__ float warpMax(float v){
    #pragma unroll
    for (int o = 16; o; o >>= 1) v = fmaxf(v, __shfl_xor_sync(0xffffffffu, v, o));
    return v;
}
__device__ __forceinline__ float warpSum(float v){
    #pragma unroll
    for (int o = 16; o; o >>= 1) v += __shfl_xor_sync(0xffffffffu, v, o);
    return v;
}
__device__ __forceinline__ float ex2(float x){
    float r; asm("ex2.approx.f32 %0, %1;" : "=f"(r) : "f"(x)); return r;
}

// Software grid barrier among the GB blocks of one slot.
// Co-residency: 256 blocks total, launch_bounds(256,2) -> capacity 296 >= 256.
__device__ __forceinline__ void gbar(int slot, unsigned &tgt){
    __syncthreads();
    if (threadIdx.x == 0){
        __threadfence();
        atomicAdd(&g_bar[slot], 1u);
        while (*((volatile unsigned*)&g_bar[slot]) < tgt) __nanosleep(32);
    }
    __syncthreads();
    tgt += GB;
}

// Convert two uint4s (16 halfs) of a K row to float.
__device__ __forceinline__ void cvt16(const uint4 &a, const uint4 &b, float *kf){
    const __half2* ha = (const __half2*)&a;
    const __half2* hb = (const __half2*)&b;
    #pragma unroll
    for (int q = 0; q < 4; q++){
        float2 f = __half22float2(ha[q]); kf[2*q]   = f.x; kf[2*q+1]   = f.y;
        float2 g = __half22float2(hb[q]); kf[8+2*q] = g.x; kf[8+2*q+1] = g.y;
    }
}

// ---------------------------------------------------------------------------
// Persistent kernel handling TWO batches concurrently (slot = high block bit).
// Phases: cmax -> exp(K16) -> 50x(rowpass -> colfix) -> argmax/loss partials.
// ---------------------------------------------------------------------------
__global__ void __launch_bounds__(NT, 2) k_persist(
        const float* __restrict__ x0p, const float* __restrict__ xgp,
        const float* __restrict__ vpp, const float* __restrict__ alp,
        int b0, unsigned base)
{
    int t = threadIdx.x, warp = t >> 5, lane = t & 31;
    int slot = blockIdx.x >> 7;             // 0..1
    int blk  = blockIdx.x & (GB - 1);       // 0..127
    const float* x0 = x0p + (size_t)slot * MPTS * 3;
    const float* xg = xgp + (size_t)slot * MPTS * 3;
    const float* vp = vpp + (size_t)slot * MPTS * 3;
    const float* al = alp + (size_t)slot * MPTS;
    __half* Kh = g_K16[slot];

    __shared__ float red[2][CR][NT];        // row-sum partials (parity buffered)
    __shared__ float su[2][CR];
    __shared__ float sr8[8];
    __shared__ float s_scalar;
    __shared__ float sB[8][33];
    __shared__ float smx[8];
    __shared__ int   smi[8];

    unsigned tgt = base + GB;
    int r0 = blk * ROWSPB;

    // Thread t owns columns j = 8t..8t+7 and 2048+8t..2048+8t+7.
    float gx[16], gy[16], gz[16];
    #pragma unroll
    for (int h = 0; h < 2; h++){
        const float* bg = xg + (size_t)h * 2048 * 3 + 24 * t;
        #pragma unroll
        for (int c = 0; c < 8; c++){
            gx[8*h+c] = bg[3*c]; gy[8*h+c] = bg[3*c+1]; gz[8*h+c] = bg[3*c+2];
        }
    }

    // ---- Phase 0: block-local cost max -----------------------------------
    {
        float mx = 0.f;
        for (int r = 0; r < ROWSPB; r++){
            int i = r0 + r;
            float ax = x0[3*i], ay = x0[3*i+1], az = x0[3*i+2];
            #pragma unroll
            for (int c = 0; c < 16; c++){
                float dx = ax-gx[c], dy = ay-gy[c], dz = az-gz[c];
                mx = fmaxf(mx, dx*dx + dy*dy + dz*dz);
            }
        }
        mx = warpMax(mx);
        if (lane == 0) sr8[warp] = mx;
        __syncthreads();
        if (t == 0){
            float m = sr8[0];
            #pragma unroll
            for (int w = 1; w < 8; w++) m = fmaxf(m, sr8[w]);
            g_cmax[slot][blk] = m;
        }
    }
    gbar(slot, tgt);

    // ---- Phase 1: global max -> scale; K16 = 2^4 * exp(-C/(reg*cmax)) ----
    {
        float mc = (t < GB) ? __ldcg(&g_cmax[slot][t]) : 0.f;
        mc = warpMax(mc);
        if (lane == 0) sr8[warp] = mc;
        __syncthreads();
        if (t == 0){
            float m = sr8[0];
            #pragma unroll
            for (int w = 1; w < 8; w++) m = fmaxf(m, sr8[w]);
            s_scalar = -1.44269504088896340736f / (0.1f * m);
        }
        __syncthreads();
        float scale = s_scalar;
        for (int r = 0; r < ROWSPB; r++){
            int i = r0 + r;
            float ax = x0[3*i], ay = x0[3*i+1], az = x0[3*i+2];
            __half2 hk[8];
            #pragma unroll
            for (int c = 0; c < 16; c += 2){
                float dx = ax-gx[c],   dy = ay-gy[c],   dz = az-gz[c];
                float e0 = ex2(fmaf(dx*dx + dy*dy + dz*dz, scale, 4.0f));
                dx = ax-gx[c+1]; dy = ay-gy[c+1]; dz = az-gz[c+1];
                float e1 = ex2(fmaf(dx*dx + dy*dy + dz*dz, scale, 4.0f));
                hk[c/2] = __floats2half2_rn(e0, e1);
            }
            uint4* Krow = (uint4*)(Kh + (size_t)i * MPTS);
            Krow[t]       = *(uint4*)&hk[0];
            Krow[256 + t] = *(uint4*)&hk[4];
        }
        if (blk == 0){
            #pragma unroll
            for (int q = 0; q < 16; q++) g_v[slot][t + 256*q] = 1.0f;
        }
    }
    gbar(slot, tgt);

    // ---- Phase 2: 50 Sinkhorn iterations ---------------------------------
    for (int it = 0; it < NITERS; it++){
        float vr[16];
        {
            float4 v0 = __ldcg((const float4*)(g_v[slot] + 8*t));
            float4 v1 = __ldcg((const float4*)(g_v[slot] + 8*t + 4));
            float4 v2 = __ldcg((const float4*)(g_v[slot] + 2048 + 8*t));
            float4 v3 = __ldcg((const float4*)(g_v[slot] + 2048 + 8*t + 4));
            vr[0]=v0.x; vr[1]=v0.y; vr[2]=v0.z;  vr[3]=v0.w;
            vr[4]=v1.x; vr[5]=v1.y; vr[6]=v1.z;  vr[7]=v1.w;
            vr[8]=v2.x; vr[9]=v2.y; vr[10]=v2.z; vr[11]=v2.w;
            vr[12]=v3.x; vr[13]=v3.y; vr[14]=v3.z; vr[15]=v3.w;
        }
        float Tacc[16];
        #pragma unroll
        for (int c = 0; c < 16; c++) Tacc[c] = 0.f;

        #pragma unroll 1
        for (int ch = 0; ch < NCH; ch++){
            int ib = r0 + ch * CR;
            int p = ch & 1;
            // Pass A: 8 independent row sums, no syncs (deep MLP)
            #pragma unroll
            for (int r = 0; r < CR; r++){
                const uint4* Kr = (const uint4*)(Kh + (size_t)(ib + r) * MPTS);
                uint4 ka = Kr[t], kb = Kr[256 + t];
                float kf[16];
                cvt16(ka, kb, kf);
                float s = 0.f;
                #pragma unroll
                for (int c = 0; c < 16; c++) s = fmaf(kf[c], vr[c], s);
                red[p][r][t] = s;
            }
            __syncthreads();
            // Block reduce: warp w reduces row w (8 rows in parallel)
            {
                float S = 0.f;
                #pragma unroll
                for (int q = 0; q < 8; q++) S += red[p][warp][lane + 32*q];
                S = warpSum(S);
                if (lane == 0){
                    float u = INV_N / S;
                    su[p][warp] = u;
                    g_u[slot][ib + warp] = u;
                }
            }
            __syncthreads();
            // Pass B: re-read same rows (L1-hot), accumulate column partials
            #pragma unroll
            for (int r = 0; r < CR; r++){
                const uint4* Kr = (const uint4*)(Kh + (size_t)(ib + r) * MPTS);
                uint4 ka = Kr[t], kb = Kr[256 + t];
                float kf[16];
                cvt16(ka, kb, kf);
                float u = su[p][r];
                #pragma unroll
                for (int c = 0; c < 16; c++) Tacc[c] = fmaf(kf[c], u, Tacc[c]);
            }
        }
        // store column partials
        float4* Tp = (float4*)&g_T[slot][blk][0];
        Tp[2*t]       = make_float4(Tacc[0],  Tacc[1],  Tacc[2],  Tacc[3]);
        Tp[2*t+1]     = make_float4(Tacc[4],  Tacc[5],  Tacc[6],  Tacc[7]);
        Tp[512+2*t]   = make_float4(Tacc[8],  Tacc[9],  Tacc[10], Tacc[11]);
        Tp[512+2*t+1] = make_float4(Tacc[12], Tacc[13], Tacc[14], Tacc[15]);
        gbar(slot, tgt);

        // Column fix: block handles 32 columns; 8 groups of 16 partials
        {
            int c = t & 31, pg = t >> 5;
            int j = blk * 32 + c;
            float s = 0.f;
            #pragma unroll
            for (int q = 0; q < 16; q++) s += __ldcg(&g_T[slot][pg*16 + q][j]);
            sB[pg][c] = s;
            __syncthreads();
            if (t < 32){
                float T = 0.f;
                #pragma unroll
                for (int g = 0; g < 8; g++) T += sB[g][t];
                g_v[slot][blk*32 + t] = INV_N / T;
            }
        }
        gbar(slot, tgt);
    }

    // ---- Phase 3: argmax of pi = u*K*v, survival, loss partials ----------
    {
        float vr[16];
        {
            float4 v0 = __ldcg((const float4*)(g_v[slot] + 8*t));
            float4 v1 = __ldcg((const float4*)(g_v[slot] + 8*t + 4));
            float4 v2 = __ldcg((const float4*)(g_v[slot] + 2048 + 8*t));
            float4 v3 = __ldcg((const float4*)(g_v[slot] + 2048 + 8*t + 4));
            vr[0]=v0.x; vr[1]=v0.y; vr[2]=v0.z;  vr[3]=v0.w;
            vr[4]=v1.x; vr[5]=v1.y; vr[6]=v1.z;  vr[7]=v1.w;
            vr[8]=v2.x; vr[9]=v2.y; vr[10]=v2.z; vr[11]=v2.w;
            vr[12]=v3.x; vr[13]=v3.y; vr[14]=v3.z; vr[15]=v3.w;
        }
        float cnt = 0.f, velsq = 0.f, bce = 0.f;   // thread 0 accumulates
        for (int r = 0; r < ROWSPB; r++){
            int i = r0 + r;
            const uint4* Kr = (const uint4*)(Kh + (size_t)i * MPTS);
            uint4 ka = Kr[t], kb = Kr[256 + t];
            float kf[16];
            cvt16(ka, kb, kf);
            float m = -1.f; int mi = 0;
            #pragma unroll
            for (int c = 0; c < 16; c++){
                float p = kf[c] * vr[c];
                int j = (c < 8) ? (8*t + c) : (2048 + 8*t + c - 8);
                if (p > m){ m = p; mi = j; }
            }
            #pragma unroll
            for (int o = 16; o; o >>= 1){
                float om = __shfl_xor_sync(0xffffffffu, m, o);
                int   oi = __shfl_xor_sync(0xffffffffu, mi, o);
                if (om > m || (om == m && oi < mi)){ m = om; mi = oi; }
            }
            if (lane == 0){ smx[warp] = m; smi[warp] = mi; }
            __syncthreads();
            if (t == 0){
                #pragma unroll
                for (int w = 1; w < 8; w++){
                    if (smx[w] > m || (smx[w] == m && smi[w] < mi)){
                        m = smx[w]; mi = smi[w];
                    }
                }
                float p = g_u[slot][i] * m;
                float a_i = al[i];
                float sp = fmaxf(a_i, 0.f) + log1pf(expf(-fabsf(a_i)));
                bce += sp;
                if (p > SURV_THRESH){
                    cnt += 1.f;
                    bce -= a_i;
                    #pragma unroll
                    for (int d = 0; d < 3; d++){
                        float vt = xg[3*mi + d] - x0[3*i + d];
                        float df = vp[3*i + d] - vt;
                        velsq = fmaf(df, df, velsq);
                    }
                }
            }
            __syncthreads();
        }
        if (t == 0){
            g_loss[b0 + slot][blk][0] = cnt;
            g_loss[b0 + slot][blk][1] = velsq;
            g_loss[b0 + slot][blk][2] = bce;
        }
    }
}

// ---------------------------------------------------------------------------
__global__ void k_reset(){ g_bar[0] = 0u; g_bar[1] = 0u; }

__global__ void __launch_bounds__(NT) k_loss(float* __restrict__ out){
    int t = threadIdx.x;
    float cnt = 0.f, velsq = 0.f, bce = 0.f;
    for (int idx = t; idx < NBATCH * GB; idx += NT){
        int b = idx / GB, p = idx % GB;
        cnt   += g_loss[b][p][0];
        velsq += g_loss[b][p][1];
        bce   += g_loss[b][p][2];
    }
    cnt = warpSum(cnt); velsq = warpSum(velsq); bce = warpSum(bce);
    __shared__ float sc[8], sv[8], sb[8];
    if ((t & 31) == 0){ sc[t>>5] = cnt; sv[t>>5] = velsq; sb[t>>5] = bce; }
    __syncthreads();
    if (t == 0){
        float C = 0.f, V = 0.f, Bc = 0.f;
        #pragma unroll
        for (int w = 0; w < 8; w++){ C += sc[w]; V += sv[w]; Bc += sb[w]; }
        float denom = fmaxf(C, 1.f);
        out[0] = V / denom + Bc / (float)(NBATCH * MPTS);
    }
}

// ---------------------------------------------------------------------------
extern "C" void kernel_launch(void* const* d_in, const int* in_sizes, int n_in,
                              void* d_out, int out_size){
    const float* x0 = (const float*)d_in[0];   // (B, M, 3)
    const float* xg = (const float*)d_in[1];   // (B, K, 3)
    const float* vp = (const float*)d_in[2];   // (B, M, 3)
    const float* al = (const float*)d_in[3];   // (B, M, 1)
    (void)in_sizes; (void)n_in; (void)out_size;

    k_reset<<<1, 1>>>();
    for (int l = 0; l < NBATCH / NSLOTS; l++){
        int b0 = l * NSLOTS;
        k_persist<<<NSLOTS * GB, NT>>>(x0 + (size_t)b0 * MPTS * 3,
                                       xg + (size_t)b0 * MPTS * 3,
                                       vp + (size_t)b0 * MPTS * 3,
                                       al + (size_t)b0 * MPTS,
                                       b0, (unsigned)(l * NBARS * GB));
    }
    k_loss<<<1, NT>>>((float*)d_out);
}